// round 1
// baseline (speedup 1.0000x reference)
#include <cuda_runtime.h>
#include <math.h>

#define Tn 1024
#define Bn 8
#define Dn 512
#define Hn 8
#define DHn 64
#define NPAIR 64           // Hn*Bn
#define ROWS (Bn*Tn)       // 8192

// ---------------- scratch (device globals: allocation-free) ----------------
__device__ float g_xb[Bn*Tn*Dn];
__device__ float g_Q [Bn*Tn*Dn];
__device__ float g_K [Bn*Tn*Dn];
__device__ float g_V [Bn*Tn*Dn];
__device__ float g_tmp[Bn*Tn*Dn];
__device__ float g_S[(size_t)NPAIR*Tn*Tn];   // 256 MB score scratch
__device__ float g_invnorm[Bn*Dn];
__device__ float g_adj[Tn];

__device__ __forceinline__ float powtf(float v){
    return sqrtf(fmaxf(v,0.f)) - sqrtf(fmaxf(-v,0.f));
}

// ---------------- transposes ----------------
__global__ void k_transpose_in(const float* __restrict__ x){
    int idx = blockIdx.x*256 + threadIdx.x;          // [B,T,D] linear
    int d = idx & (Dn-1);
    int t = (idx >> 9) & (Tn-1);
    int b = idx >> 19;
    g_xb[idx] = x[(t*Bn + b)*Dn + d];
}

__global__ void k_transpose_out(float* __restrict__ out){
    int idx = blockIdx.x*256 + threadIdx.x;          // [T,B,D] linear
    int d = idx & (Dn-1);
    int b = (idx >> 9) & (Bn-1);
    int t = idx >> 12;
    out[idx] = g_xb[((b<<10) + t)*Dn + d];
}

// ---------------- adj table ----------------
__global__ void k_adj(const float* __restrict__ aw, const float* __restrict__ ab){
    int i = threadIdx.x;
    float dist = (float)i;
    g_adj[i] = expf(-fabsf(aw[0]*dist*dist - ab[0]));
}

// ---------------- QKV GEMM: C = xb @ W + b ----------------
__global__ __launch_bounds__(256) void k_gemm_qkv(
    const float* __restrict__ Wq, const float* __restrict__ Wk, const float* __restrict__ Wv,
    const float* __restrict__ bq, const float* __restrict__ bk, const float* __restrict__ bv,
    int layer)
{
    __shared__ __align__(16) float As[16][65];   // [k][m]
    __shared__ __align__(16) float Bs[16][68];   // [k][n]
    int tid = threadIdx.x;
    int z = blockIdx.z;
    const float* W    = (z==0 ? Wq : (z==1 ? Wk : Wv)) + layer*Dn*Dn;
    const float* bias = (z==0 ? bq : (z==1 ? bk : bv)) + layer*Dn;
    float* C          = (z==0 ? g_Q : (z==1 ? g_K : g_V));
    int m0 = blockIdx.y*64, n0 = blockIdx.x*64;
    int tx = tid & 15, ty = tid >> 4;
    int ar = tid >> 2, ac = (tid & 3) << 2;
    int br = tid >> 4, bc = (tid & 15) << 2;
    float acc[4][4] = {};
    for (int k0 = 0; k0 < Dn; k0 += 16){
        float4 a4 = *(const float4*)&g_xb[(m0+ar)*Dn + k0 + ac];
        As[ac+0][ar]=a4.x; As[ac+1][ar]=a4.y; As[ac+2][ar]=a4.z; As[ac+3][ar]=a4.w;
        *(float4*)&Bs[br][bc] = *(const float4*)&W[(size_t)(k0+br)*Dn + n0 + bc];
        __syncthreads();
#pragma unroll
        for (int kk=0; kk<16; kk++){
            float ra[4], rb[4];
#pragma unroll
            for (int i=0;i<4;i++) ra[i]=As[kk][ty*4+i];
#pragma unroll
            for (int j=0;j<4;j++) rb[j]=Bs[kk][tx*4+j];
#pragma unroll
            for (int i=0;i<4;i++)
#pragma unroll
                for (int j=0;j<4;j++) acc[i][j] = fmaf(ra[i], rb[j], acc[i][j]);
        }
        __syncthreads();
    }
    float4 b4 = *(const float4*)&bias[n0 + tx*4];
#pragma unroll
    for (int i=0;i<4;i++){
        float4 v;
        v.x=acc[i][0]+b4.x; v.y=acc[i][1]+b4.y; v.z=acc[i][2]+b4.z; v.w=acc[i][3]+b4.w;
        *(float4*)&C[(size_t)(m0+ty*4+i)*Dn + n0 + tx*4] = v;
    }
}

// ---------------- S = Q K^T * scale + adj, per (h,b) pair ----------------
__global__ __launch_bounds__(256) void k_attn_s(){
    __shared__ __align__(16) float Qs[64][68];   // [qrow][dh]
    __shared__ float Ks[64][65];                 // transposed: [dh][krow]
    int tid = threadIdx.x;
    int p = blockIdx.z;
    const float* Qp = g_Q + (size_t)p*Tn*DHn;
    const float* Kp = g_K + (size_t)p*Tn*DHn;
    int q0 = blockIdx.y*64, k0 = blockIdx.x*64;
#pragma unroll
    for (int i=0;i<4;i++){
        int idx = tid + i*256;
        int r = idx >> 4, c = (idx & 15) << 2;
        *(float4*)&Qs[r][c] = *(const float4*)&Qp[(q0+r)*DHn + c];
        float4 kv = *(const float4*)&Kp[(k0+r)*DHn + c];
        Ks[c+0][r]=kv.x; Ks[c+1][r]=kv.y; Ks[c+2][r]=kv.z; Ks[c+3][r]=kv.w;
    }
    __syncthreads();
    int tx = tid & 15, ty = tid >> 4;
    float acc[4][4]={};
#pragma unroll
    for (int kk=0; kk<64; kk++){
        float ra[4], rb[4];
#pragma unroll
        for (int i=0;i<4;i++) ra[i]=Qs[ty*4+i][kk];
#pragma unroll
        for (int j=0;j<4;j++) rb[j]=Ks[kk][tx*4+j];
#pragma unroll
        for (int i=0;i<4;i++)
#pragma unroll
            for (int j=0;j<4;j++) acc[i][j] = fmaf(ra[i], rb[j], acc[i][j]);
    }
    const float scale = 0.04419417382415922f;    // 1/sqrt(512)
#pragma unroll
    for (int i=0;i<4;i++){
        int q = q0 + ty*4 + i;
        float4 v;
        int kbase = k0 + tx*4;
        v.x = acc[i][0]*scale + g_adj[abs(q-(kbase+0))];
        v.y = acc[i][1]*scale + g_adj[abs(q-(kbase+1))];
        v.z = acc[i][2]*scale + g_adj[abs(q-(kbase+2))];
        v.w = acc[i][3]*scale + g_adj[abs(q-(kbase+3))];
        *(float4*)&g_S[((size_t)p*Tn + q)*Tn + kbase] = v;
    }
}

// ---------------- combined softmax: P = a*softmax_global + (1-a)*softmax_window ----------------
__global__ __launch_bounds__(128) void k_softmax(const float* __restrict__ alpha, int layer){
    __shared__ float shm[10];
    size_t row = blockIdx.x;
    int q = (int)(row & (Tn-1));
    float* Srow = g_S + row*Tn;
    int tid = threadIdx.x, lane = tid&31, wid = tid>>5;

    float s[8];
    float m = -1e30f;
#pragma unroll
    for (int j=0;j<8;j++){ s[j] = Srow[tid + j*128]; m = fmaxf(m, s[j]); }
#pragma unroll
    for (int o=16;o;o>>=1) m = fmaxf(m, __shfl_xor_sync(0xffffffffu,m,o));
    if (lane==0) shm[wid]=m;
    __syncthreads();
    if (tid==0) shm[4] = fmaxf(fmaxf(shm[0],shm[1]),fmaxf(shm[2],shm[3]));
    __syncthreads();
    float gmax = shm[4];

    float e[8]; float sum=0.f;
#pragma unroll
    for (int j=0;j<8;j++){ e[j] = expf(s[j]-gmax); sum += e[j]; }
#pragma unroll
    for (int o=16;o;o>>=1) sum += __shfl_xor_sync(0xffffffffu,sum,o);
    if (lane==0) shm[wid]=sum;
    __syncthreads();
    if (tid==0){
        shm[5] = shm[0]+shm[1]+shm[2]+shm[3];
        int lo = q-4; if (lo<0) lo=0;
        int hi = q+4; if (hi>Tn-1) hi=Tn-1;
        float lm=-1e30f;
        for (int k=lo;k<=hi;k++) lm = fmaxf(lm, Srow[k]);
        float ls=0.f;
        for (int k=lo;k<=hi;k++) ls += expf(Srow[k]-lm);
        shm[6]=lm; shm[7]=1.f/ls;
    }
    __syncthreads();
    float a    = 1.f/(1.f+expf(-alpha[layer]));
    float ginv = a/shm[5];
    float lm   = shm[6];
    float linv = (1.f-a)*shm[7];
    int lo = (q-4>0)? q-4 : 0;
    int hi = (q+4<Tn-1)? q+4 : Tn-1;
#pragma unroll
    for (int j=0;j<8;j++){
        int k = tid + j*128;
        float v = e[j]*ginv;
        if (k>=lo && k<=hi) v += expf(s[j]-lm)*linv;
        Srow[k] = v;
    }
}

// ---------------- O = P @ V, fused power transform ----------------
__global__ __launch_bounds__(256) void k_pv(){
    __shared__ __align__(16) float Ps[64][36];   // [qrow][k]
    __shared__ __align__(16) float Vs[32][68];   // [k][dh]
    int tid = threadIdx.x;
    int p  = blockIdx.y;
    int q0 = blockIdx.x*64;
    const float* Vp = g_V + (size_t)p*Tn*DHn;
    const float* Sp = g_S + (size_t)p*Tn*Tn;
    int tx = tid&15, ty = tid>>4;
    float acc[4][4]={};
    for (int k0=0;k0<Tn;k0+=32){
#pragma unroll
        for (int i=0;i<2;i++){
            int idx = tid + i*256;
            int r  = idx>>3, c  = (idx&7)<<2;
            *(float4*)&Ps[r][c]   = *(const float4*)&Sp[(size_t)(q0+r)*Tn + k0 + c];
            int vr = idx>>4, vc = (idx&15)<<2;
            *(float4*)&Vs[vr][vc] = *(const float4*)&Vp[(k0+vr)*DHn + vc];
        }
        __syncthreads();
#pragma unroll
        for (int kk=0;kk<32;kk++){
            float ra[4],rb[4];
#pragma unroll
            for (int i=0;i<4;i++) ra[i]=Ps[ty*4+i][kk];
#pragma unroll
            for (int j=0;j<4;j++) rb[j]=Vs[kk][tx*4+j];
#pragma unroll
            for (int i=0;i<4;i++)
#pragma unroll
                for (int j=0;j<4;j++) acc[i][j] = fmaf(ra[i], rb[j], acc[i][j]);
        }
        __syncthreads();
    }
#pragma unroll
    for (int i=0;i<4;i++){
        int q = q0 + ty*4 + i;
        float4 v;
        v.x = powtf(acc[i][0]); v.y = powtf(acc[i][1]);
        v.z = powtf(acc[i][2]); v.w = powtf(acc[i][3]);
        *(float4*)&g_tmp[(size_t)p*Tn*DHn + q*DHn + tx*4] = v;
    }
}

// ---------------- column L2 norms over seq axis (per b,d) ----------------
__global__ void k_colnorm(){
    int tid = threadIdx.x;
    int col = blockIdx.x*8 + (tid>>5);   // 0..4095
    int lane = tid&31;
    int b = col >> 9, d = col & (Dn-1);
    const float* base = g_tmp + (size_t)b*Tn*Dn + d;
    float sum = 0.f;
    for (int t=lane; t<Tn; t+=32){ float v = base[(size_t)t*Dn]; sum = fmaf(v,v,sum); }
#pragma unroll
    for (int o=16;o;o>>=1) sum += __shfl_xor_sync(0xffffffffu,sum,o);
    if (lane==0) g_invnorm[col] = 1.f/fmaxf(sqrtf(sum), 1e-12f);
}

// ---------------- out proj: xb = xb + (tmp/norm) @ Wo + bo ----------------
__global__ __launch_bounds__(256) void k_gemm_out(
    const float* __restrict__ Wo, const float* __restrict__ bo, int layer)
{
    __shared__ __align__(16) float As[16][65];
    __shared__ __align__(16) float Bs[16][68];
    int tid = threadIdx.x;
    const float* W    = Wo + (size_t)layer*Dn*Dn;
    const float* bias = bo + layer*Dn;
    int m0 = blockIdx.y*64, n0 = blockIdx.x*64;
    int tx = tid & 15, ty = tid >> 4;
    int ar = tid >> 2, ac = (tid & 3) << 2;
    int br = tid >> 4, bc = (tid & 15) << 2;
    float acc[4][4] = {};
    for (int k0 = 0; k0 < Dn; k0 += 16){
        int arow = m0+ar;
        float4 a4 = *(const float4*)&g_tmp[(size_t)arow*Dn + k0 + ac];
        float4 s4 = *(const float4*)&g_invnorm[(arow>>10)*Dn + k0 + ac];
        a4.x*=s4.x; a4.y*=s4.y; a4.z*=s4.z; a4.w*=s4.w;
        As[ac+0][ar]=a4.x; As[ac+1][ar]=a4.y; As[ac+2][ar]=a4.z; As[ac+3][ar]=a4.w;
        *(float4*)&Bs[br][bc] = *(const float4*)&W[(size_t)(k0+br)*Dn + n0 + bc];
        __syncthreads();
#pragma unroll
        for (int kk=0; kk<16; kk++){
            float ra[4], rb[4];
#pragma unroll
            for (int i=0;i<4;i++) ra[i]=As[kk][ty*4+i];
#pragma unroll
            for (int j=0;j<4;j++) rb[j]=Bs[kk][tx*4+j];
#pragma unroll
            for (int i=0;i<4;i++)
#pragma unroll
                for (int j=0;j<4;j++) acc[i][j] = fmaf(ra[i], rb[j], acc[i][j]);
        }
        __syncthreads();
    }
    float4 b4 = *(const float4*)&bias[n0 + tx*4];
#pragma unroll
    for (int i=0;i<4;i++){
        int m = m0+ty*4+i;
        float4 r4 = *(const float4*)&g_xb[(size_t)m*Dn + n0 + tx*4];
        float4 v;
        v.x=acc[i][0]+b4.x+r4.x; v.y=acc[i][1]+b4.y+r4.y;
        v.z=acc[i][2]+b4.z+r4.z; v.w=acc[i][3]+b4.w+r4.w;
        *(float4*)&g_xb[(size_t)m*Dn + n0 + tx*4] = v;
    }
}

// ---------------- LayerNorm over D, in place on g_xb ----------------
__global__ __launch_bounds__(128) void k_ln(
    const float* __restrict__ lng, const float* __restrict__ lnb, int layer)
{
    __shared__ float shm[10];
    int r = blockIdx.x;
    int tid = threadIdx.x, lane = tid&31, wid = tid>>5;
    float v[4];
    float sum=0.f, sq=0.f;
#pragma unroll
    for (int j=0;j<4;j++){
        v[j] = g_xb[(size_t)r*Dn + tid + j*128];
        sum += v[j]; sq = fmaf(v[j],v[j],sq);
    }
#pragma unroll
    for (int o=16;o;o>>=1){ sum += __shfl_xor_sync(0xffffffffu,sum,o); sq += __shfl_xor_sync(0xffffffffu,sq,o); }
    if (lane==0){ shm[wid]=sum; shm[4+wid]=sq; }
    __syncthreads();
    if (tid==0){ shm[8]=shm[0]+shm[1]+shm[2]+shm[3]; shm[9]=shm[4]+shm[5]+shm[6]+shm[7]; }
    __syncthreads();
    float mu  = shm[8]*(1.f/Dn);
    float var = shm[9]*(1.f/Dn) - mu*mu;
    float rstd = rsqrtf(fmaxf(var,0.f) + 1e-5f);
    const float* g  = lng + layer*Dn;
    const float* bb = lnb + layer*Dn;
#pragma unroll
    for (int j=0;j<4;j++){
        int d = tid + j*128;
        g_xb[(size_t)r*Dn + d] = (v[j]-mu)*rstd*g[d] + bb[d];
    }
}

// ---------------- launch ----------------
extern "C" void kernel_launch(void* const* d_in, const int* in_sizes, int n_in,
                              void* d_out, int out_size)
{
    const float* x     = (const float*)d_in[0];
    const float* Wq    = (const float*)d_in[1];
    const float* bq    = (const float*)d_in[2];
    const float* Wk    = (const float*)d_in[3];
    const float* bk    = (const float*)d_in[4];
    const float* Wv    = (const float*)d_in[5];
    const float* bv    = (const float*)d_in[6];
    const float* Wo    = (const float*)d_in[7];
    const float* bo    = (const float*)d_in[8];
    const float* alpha = (const float*)d_in[9];
    const float* ln_g  = (const float*)d_in[10];
    const float* ln_b  = (const float*)d_in[11];
    const float* adj_w = (const float*)d_in[12];
    const float* adj_b = (const float*)d_in[13];
    float* out = (float*)d_out;

    k_transpose_in<<<(ROWS*Dn)/256, 256>>>(x);
    k_adj<<<1, Tn>>>(adj_w, adj_b);
    for (int l=0; l<2; l++){
        k_gemm_qkv<<<dim3(8,128,3), 256>>>(Wq,Wk,Wv,bq,bk,bv,l);
        k_attn_s<<<dim3(16,16,64), 256>>>();
        k_softmax<<<NPAIR*Tn, 128>>>(alpha, l);
        k_pv<<<dim3(16,64), 256>>>();
        k_colnorm<<<512, 256>>>();
        k_gemm_out<<<dim3(8,128), 256>>>(Wo, bo, l);
        k_ln<<<ROWS, 128>>>(ln_g, ln_b, l);
    }
    k_transpose_out<<<(ROWS*Dn)/256, 256>>>(out);
}